// round 14
// baseline (speedup 1.0000x reference)
#include <cuda_runtime.h>
#include <cuda_bf16.h>
#include <math.h>

// Problem constants
#define TT 256
#define BB 64
#define EE 300
#define HH 256
#define KK 20
#define GN 2048   // concat gate width: 2 dirs * 4 gates * H
#define NR 1024   // gate rows per direction (4*H)

// ---------------- scratch (__device__ globals: allocation-free, zero-init) ----------------
__device__ float d_embx[(size_t)TT * BB * EE];      // embedded input  [T*B, 300]
__device__ float d_xg  [(size_t)TT * BB * GN];      // gate pre-acts   [T*B, 2048] (reused per layer)
__device__ float d_out0[(size_t)TT * BB * 512];     // layer0 output   [T*B, 512]
__device__ float d_out1[(size_t)TT * BB * 512];     // layer1 output   [T*B, 512]
__device__ float d_emis[(size_t)TT * BB * KK];      // emissions       [T*B, 20]
__device__ float d_whhT[2 * HH * NR];               // transposed Whh  [dir][j][row]
__device__ float d_h[2 * BB * HH];                  // h state [dir][b][u]
__device__ float d_c[2 * BB * HH];                  // c state [dir][b][u]
__device__ int   d_vptr[(size_t)TT * BB * KK];      // viterbi backpointers

// ---------------- embedding gather ----------------
__global__ void __launch_bounds__(128) emb_kernel(const int* __restrict__ x,
                                                  const float* __restrict__ emb) {
    int row = blockIdx.x;                 // row = t*B + b
    int tok = x[row];
    const float* s = emb + (size_t)tok * EE;
    float* d = d_embx + (size_t)row * EE;
    for (int e = threadIdx.x; e < EE; e += 128) d[e] = s[e];
}

// ---------------- input-projection GEMM: C[M,2048] = A[M,K] @ W[2048,K]^T + bias ----------------
#define BM 64
#define BN 64
#define BKT 16
__global__ void __launch_bounds__(256) gemm_xg(const float* __restrict__ Bw,
                                               const float* __restrict__ bias,
                                               int layer, int K) {
    const float* A = (layer == 0) ? d_embx : d_out0;
    __shared__ float As[BKT][BM + 4];
    __shared__ float Bs[BKT][BN + 4];
    int m0 = blockIdx.y * BM;
    int n0 = blockIdx.x * BN;
    int tid = threadIdx.x;
    int tx = tid & 15, ty = tid >> 4;
    float acc[4][4];
#pragma unroll
    for (int i = 0; i < 4; i++)
#pragma unroll
        for (int j = 0; j < 4; j++) acc[i][j] = 0.f;

    for (int k0 = 0; k0 < K; k0 += BKT) {
#pragma unroll
        for (int r = 0; r < 4; r++) {
            int idx = tid + r * 256;       // 0..1023
            int mm = idx >> 4;             // 0..63
            int kk = idx & 15;
            int kg = k0 + kk;
            As[kk][mm] = (kg < K) ? A [(size_t)(m0 + mm) * K + kg] : 0.f;
            Bs[kk][mm] = (kg < K) ? Bw[(size_t)(n0 + mm) * K + kg] : 0.f;
        }
        __syncthreads();
#pragma unroll
        for (int k = 0; k < BKT; k++) {
            float4 a4 = *(const float4*)&As[k][ty * 4];
            float4 b4 = *(const float4*)&Bs[k][tx * 4];
            float a[4] = {a4.x, a4.y, a4.z, a4.w};
            float b[4] = {b4.x, b4.y, b4.z, b4.w};
#pragma unroll
            for (int i = 0; i < 4; i++)
#pragma unroll
                for (int j = 0; j < 4; j++) acc[i][j] += a[i] * b[j];
        }
        __syncthreads();
    }
#pragma unroll
    for (int i = 0; i < 4; i++) {
        int m = m0 + ty * 4 + i;
#pragma unroll
        for (int j = 0; j < 4; j++) {
            int n = n0 + tx * 4 + j;
            d_xg[(size_t)m * GN + n] = acc[i][j] + bias[n];
        }
    }
}

// ---------------- Whh transpose: [dir][row 1024][j 256] -> d_whhT [dir][j 256][row 1024] ----------------
__global__ void __launch_bounds__(256) transpose_whh(const float* __restrict__ W) {
    __shared__ float t[32][33];
    int dir = blockIdx.z;
    int r0 = blockIdx.x * 32;      // row tile (gridDim.x = 32)
    int j0 = blockIdx.y * 32;      // col tile (gridDim.y = 8)
    int tx = threadIdx.x & 31;
    int ty = threadIdx.x >> 5;     // 0..7
#pragma unroll
    for (int k = 0; k < 32; k += 8)
        t[ty + k][tx] = W[(size_t)dir * NR * HH + (size_t)(r0 + ty + k) * HH + (j0 + tx)];
    __syncthreads();
#pragma unroll
    for (int k = 0; k < 32; k += 8)
        d_whhT[(size_t)dir * HH * NR + (size_t)(j0 + ty + k) * NR + (r0 + tx)] = t[tx][ty + k];
}

// ---------------- one LSTM time step (both dirs): grid 64 = dir*32 + bpair, block 512 ----------------
__global__ void __launch_bounds__(512) lstm_step(const int* __restrict__ lens,
                                                 int layer, int s) {
    __shared__ float h_sm[2][HH];      // h_{s-1} for the 2 batch elements
    __shared__ float g_sm[2][NR];      // gate pre-activations
    int dir = blockIdx.x >> 5;
    int bp  = blockIdx.x & 31;
    int tid = threadIdx.x;
    float* outp = (layer == 0) ? d_out0 : d_out1;

    // stage h_prev: 512 threads -> (bl, j)
    int bl = tid >> 8, j = tid & 255;
    int b  = bp * 2 + bl;
    h_sm[bl][j] = (s == 0) ? 0.f : d_h[(dir * BB + b) * HH + j];
    __syncthreads();

    int len0 = lens[bp * 2 + 0];
    int len1 = lens[bp * 2 + 1];
    int trow0 = (dir == 0) ? s : ((s < len0) ? (len0 - 1 - s) : s);
    int trow1 = (dir == 0) ? s : ((s < len1) ? (len1 - 1 - s) : s);

    // gate dots: thread handles rows tid and tid+512 for both batch elements
    float a00 = 0.f, a01 = 0.f, a10 = 0.f, a11 = 0.f;   // [rowhalf][bl]
    const float* wt = d_whhT + (size_t)dir * HH * NR;
#pragma unroll 8
    for (int jj = 0; jj < HH; jj++) {
        float w0 = wt[(size_t)jj * NR + tid];
        float w1 = wt[(size_t)jj * NR + tid + 512];
        float h0 = h_sm[0][jj];
        float h1 = h_sm[1][jj];
        a00 += w0 * h0; a01 += w0 * h1;
        a10 += w1 * h0; a11 += w1 * h1;
    }
    {
        const float* x0 = d_xg + (size_t)(trow0 * BB + bp * 2 + 0) * GN + dir * NR;
        const float* x1 = d_xg + (size_t)(trow1 * BB + bp * 2 + 1) * GN + dir * NR;
        g_sm[0][tid]       = a00 + x0[tid];
        g_sm[1][tid]       = a01 + x1[tid];
        g_sm[0][tid + 512] = a10 + x0[tid + 512];
        g_sm[1][tid + 512] = a11 + x1[tid + 512];
    }
    __syncthreads();

    // pointwise: thread -> (bl, u)
    int u = j;
    int lenb = bl ? len1 : len0;
    int trow = bl ? trow1 : trow0;
    float gi = g_sm[bl][u];
    float gf = g_sm[bl][256 + u];
    float gg = g_sm[bl][512 + u];
    float go = g_sm[bl][768 + u];
    float c  = (s == 0) ? 0.f : d_c[(dir * BB + b) * HH + u];
    float si = 1.f / (1.f + expf(-gi));
    float sf = 1.f / (1.f + expf(-gf));
    float so = 1.f / (1.f + expf(-go));
    float cn = sf * c + si * tanhf(gg);
    float hn = so * tanhf(cn);
    bool  m  = (s < lenb);                       // pack_padded freeze semantics
    float hq = h_sm[bl][u];                      // previous h (frozen at padded steps)
    d_c[(dir * BB + b) * HH + u] = m ? cn : c;
    d_h[(dir * BB + b) * HH + u] = m ? hn : hq;
    // bwd writes through rev (involution) -> natural time order directly
    outp[(size_t)(trow * BB + b) * 512 + dir * HH + u] = m ? hn : 0.f;
}

// ---------------- emissions: warp per (t,b) row, 20 outputs over 512 features ----------------
__global__ void __launch_bounds__(256) emis_kernel(const float* __restrict__ Wo,
                                                   const float* __restrict__ bo) {
    int w = (blockIdx.x * 256 + threadIdx.x) >> 5;
    int lane = threadIdx.x & 31;
    if (w >= TT * BB) return;
    const float* row = d_out1 + (size_t)w * 512;
    float rv[16];
#pragma unroll
    for (int q = 0; q < 16; q++) rv[q] = row[lane + q * 32];
    for (int k = 0; k < KK; k++) {
        const float* wp = Wo + (size_t)k * 512;
        float sacc = 0.f;
#pragma unroll
        for (int q = 0; q < 16; q++) sacc += rv[q] * wp[lane + q * 32];
#pragma unroll
        for (int o = 16; o > 0; o >>= 1) sacc += __shfl_down_sync(0xffffffffu, sacc, o);
        if (lane == 0) d_emis[(size_t)w * KK + k] = sacc + bo[k];
    }
}

// ---------------- Viterbi decode: one warp per batch element ----------------
// NOTE: output written as FLOAT32 — the harness's __output__ dtype is float
// (the JAX int32 tags are converted by the bench infra). Writing raw int bit
// patterns reinterprets as ~1e-44 denormals == numerically zero, which is
// exactly the rel_err = 1.000000e+00 observed in the two prior rounds.
__global__ void __launch_bounds__(32) viterbi_kernel(const float* __restrict__ trans,
                                                     const float* __restrict__ startv,
                                                     const float* __restrict__ endv,
                                                     const int* __restrict__ lens,
                                                     float* __restrict__ out) {
    __shared__ float tr[KK * KK];
    __shared__ float sc[KK];
    int b = blockIdx.x;
    int lane = threadIdx.x;
    int len = lens[b];
    for (int i = lane; i < KK * KK; i += 32) tr[i] = trans[i];
    if (lane < KK) sc[lane] = startv[lane] + d_emis[(size_t)(0 * BB + b) * KK + lane];
    __syncwarp();
    for (int t = 1; t < TT; t++) {
        if (t < len) {                     // padded steps: score frozen, identity ptr
            float best = -1e30f; int arg = 0;
            if (lane < KK) {
#pragma unroll
                for (int p = 0; p < KK; p++) {
                    float v = sc[p] + tr[p * KK + lane];
                    if (v > best) { best = v; arg = p; }   // first-max (jnp.argmax)
                }
                best += d_emis[(size_t)(t * BB + b) * KK + lane];
            }
            __syncwarp();
            if (lane < KK) {
                sc[lane] = best;
                d_vptr[(size_t)((t - 1) * BB + b) * KK + lane] = arg;
            }
            __syncwarp();
        }
    }
    if (lane == 0) {
        float bb = -1e30f; int last = 0;
        for (int k = 0; k < KK; k++) {
            float v = sc[k] + endv[k];
            if (v > bb) { bb = v; last = k; }
        }
        int tag = last;
        for (int t = TT - 1; t >= 1; --t) {
            if (t < len) {
                out[t * BB + b] = (float)tag;
                tag = d_vptr[(size_t)((t - 1) * BB + b) * KK + tag];
            } else {
                out[t * BB + b] = 0.f;     // identity ptr passes tag through; masked to 0
            }
        }
        out[b] = (float)tag;               // t = 0 always valid (len >= 128)
    }
}

// ---------------- launch ----------------
extern "C" void kernel_launch(void* const* d_in, const int* in_sizes, int n_in,
                              void* d_out, int out_size) {
    // Bind inputs by stable size-match against the expected setup_inputs dict order.
    // Identity mapping when metadata order == dict order; corrects any permutation
    // that preserves relative order within same-size groups.
    static const long long want[14] = {
        (long long)TT * BB,            // x              16384 (int32)
        BB,                            // sent_lengths   64    (int32)
        50000LL * EE,                  // emb            15,000,000
        2LL * NR * EE,                 // Wih0           614,400
        2LL * NR * HH,                 // Whh0           524,288
        2LL * NR,                      // b0             2,048
        2LL * NR * 2 * HH,             // Wih1           1,048,576
        2LL * NR * HH,                 // Whh1           524,288
        2LL * NR,                      // b1             2,048
        (long long)KK * 2 * HH,        // W_out          10,240
        KK,                            // b_out          20
        (long long)KK * KK,            // trans          400
        KK,                            // start          20
        KK                             // end            20
    };
    const void* p[14];
    bool used[64] = {false};
    for (int i = 0; i < 14; i++) {
        p[i] = nullptr;
        for (int k = 0; k < n_in && k < 64; k++) {
            if (!used[k] && (long long)in_sizes[k] == want[i]) {
                p[i] = d_in[k]; used[k] = true; break;
            }
        }
        if (!p[i] && i < n_in) p[i] = d_in[i];   // fallback: positional
    }
    const int*   x      = (const int*)p[0];
    const int*   lens   = (const int*)p[1];
    const float* emb    = (const float*)p[2];
    const float* Wih0   = (const float*)p[3];
    const float* Whh0   = (const float*)p[4];
    const float* b0     = (const float*)p[5];
    const float* Wih1   = (const float*)p[6];
    const float* Whh1   = (const float*)p[7];
    const float* b1     = (const float*)p[8];
    const float* Wout   = (const float*)p[9];
    const float* bout   = (const float*)p[10];
    const float* trans  = (const float*)p[11];
    const float* startv = (const float*)p[12];
    const float* endv   = (const float*)p[13];
    float* out = (float*)d_out;

    dim3 tgrid(32, 8, 2);   // Whh transpose tiles

    emb_kernel<<<TT * BB, 128>>>(x, emb);

    // ---- layer 0 ----
    gemm_xg<<<dim3(GN / BN, (TT * BB) / BM), 256>>>(Wih0, b0, 0, EE);
    transpose_whh<<<tgrid, 256>>>(Whh0);
    for (int s = 0; s < TT; s++)
        lstm_step<<<64, 512>>>(lens, 0, s);

    // ---- layer 1 ----
    gemm_xg<<<dim3(GN / BN, (TT * BB) / BM), 256>>>(Wih1, b1, 1, 2 * HH);
    transpose_whh<<<tgrid, 256>>>(Whh1);
    for (int s = 0; s < TT; s++)
        lstm_step<<<64, 512>>>(lens, 1, s);

    // ---- emissions + CRF decode ----
    emis_kernel<<<(TT * BB) / 8, 256>>>(Wout, bout);
    viterbi_kernel<<<BB, 32>>>(trans, startv, endv, lens, out);
}

// round 15
// speedup vs baseline: 2.1612x; 2.1612x over previous
#include <cuda_runtime.h>
#include <cuda_bf16.h>
#include <math.h>

// Problem constants
#define TT 256
#define BB 64
#define EE 300
#define HH 256
#define KK 20
#define GN 2048   // concat gate width: 2 dirs * 4 gates * H
#define NR 1024   // gate rows per direction (4*H)

// ---------------- scratch (__device__ globals: allocation-free, zero-init) ----------------
__device__ float d_embx[(size_t)TT * BB * EE];      // embedded input  [T*B, 300]
__device__ float d_xg  [(size_t)TT * BB * GN];      // gate pre-acts   [T*B, 2048] (reused per layer)
__device__ float d_out0[(size_t)TT * BB * 512];     // layer0 output   [T*B, 512]
__device__ float d_out1[(size_t)TT * BB * 512];     // layer1 output   [T*B, 512]
__device__ float d_emis[(size_t)TT * BB * KK];      // emissions       [T*B, 20]
__device__ float d_whhT[2 * HH * NR];               // transposed Whh  [dir][j][row]
__device__ int   d_vptr[(size_t)TT * BB * KK];      // viterbi backpointers

// ---------------- embedding gather ----------------
__global__ void __launch_bounds__(128) emb_kernel(const int* __restrict__ x,
                                                  const float* __restrict__ emb) {
    int row = blockIdx.x;                 // row = t*B + b
    int tok = x[row];
    const float* s = emb + (size_t)tok * EE;
    float* d = d_embx + (size_t)row * EE;
    for (int e = threadIdx.x; e < EE; e += 128) d[e] = s[e];
}

// ---------------- input-projection GEMM: C[M,2048] = A[M,K] @ W[2048,K]^T + bias ----------------
#define BM 64
#define BN 64
#define BKT 16
__global__ void __launch_bounds__(256) gemm_xg(const float* __restrict__ Bw,
                                               const float* __restrict__ bias,
                                               int layer, int K) {
    const float* A = (layer == 0) ? d_embx : d_out0;
    __shared__ float As[BKT][BM + 4];
    __shared__ float Bs[BKT][BN + 4];
    int m0 = blockIdx.y * BM;
    int n0 = blockIdx.x * BN;
    int tid = threadIdx.x;
    int tx = tid & 15, ty = tid >> 4;
    float acc[4][4];
#pragma unroll
    for (int i = 0; i < 4; i++)
#pragma unroll
        for (int j = 0; j < 4; j++) acc[i][j] = 0.f;

    for (int k0 = 0; k0 < K; k0 += BKT) {
#pragma unroll
        for (int r = 0; r < 4; r++) {
            int idx = tid + r * 256;       // 0..1023
            int mm = idx >> 4;             // 0..63
            int kk = idx & 15;
            int kg = k0 + kk;
            As[kk][mm] = (kg < K) ? A [(size_t)(m0 + mm) * K + kg] : 0.f;
            Bs[kk][mm] = (kg < K) ? Bw[(size_t)(n0 + mm) * K + kg] : 0.f;
        }
        __syncthreads();
#pragma unroll
        for (int k = 0; k < BKT; k++) {
            float4 a4 = *(const float4*)&As[k][ty * 4];
            float4 b4 = *(const float4*)&Bs[k][tx * 4];
            float a[4] = {a4.x, a4.y, a4.z, a4.w};
            float b[4] = {b4.x, b4.y, b4.z, b4.w};
#pragma unroll
            for (int i = 0; i < 4; i++)
#pragma unroll
                for (int j = 0; j < 4; j++) acc[i][j] += a[i] * b[j];
        }
        __syncthreads();
    }
#pragma unroll
    for (int i = 0; i < 4; i++) {
        int m = m0 + ty * 4 + i;
#pragma unroll
        for (int j = 0; j < 4; j++) {
            int n = n0 + tx * 4 + j;
            d_xg[(size_t)m * GN + n] = acc[i][j] + bias[n];
        }
    }
}

// ---------------- Whh transpose: [dir][row 1024][j 256] -> d_whhT [dir][j 256][row 1024] ----------------
__global__ void __launch_bounds__(256) transpose_whh(const float* __restrict__ W) {
    __shared__ float t[32][33];
    int dir = blockIdx.z;
    int r0 = blockIdx.x * 32;      // row tile (gridDim.x = 32)
    int j0 = blockIdx.y * 32;      // col tile (gridDim.y = 8)
    int tx = threadIdx.x & 31;
    int ty = threadIdx.x >> 5;     // 0..7
#pragma unroll
    for (int k = 0; k < 32; k += 8)
        t[ty + k][tx] = W[(size_t)dir * NR * HH + (size_t)(r0 + ty + k) * HH + (j0 + tx)];
    __syncthreads();
#pragma unroll
    for (int k = 0; k < 32; k += 8)
        d_whhT[(size_t)dir * HH * NR + (size_t)(j0 + ty + k) * NR + (r0 + tx)] = t[tx][ty + k];
}

// ---------------- persistent cluster scan ----------------
// grid = 128 CTAs: cta = dir*64 + bs*8 + rs. Cluster (8 CTAs) = one (dir, bs)
// group; rank rs owns units [rs*32, rs*32+32). Each CTA keeps its 128 Whh
// gate-rows in SMEM (transposed, [k][r]) and all 256 h features for its 8
// batch elements in a double-buffered SMEM ring, exchanged each step via
// DSMEM stores + barrier.cluster.
//
// SMEM layout (floats):
//   wT   [256][128]          32768
//   hbuf [2][8][260]          4160   (row pitch 260 -> conflict-free float4)
//   gsm  [128][9]             1152
#define HROW 260
#define HPH  (8 * HROW)
#define SM_FLOATS (256 * 128 + 2 * HPH + 128 * 9)

__device__ __forceinline__ void cluster_sync_() {
    asm volatile("barrier.cluster.arrive.aligned;" ::: "memory");
    asm volatile("barrier.cluster.wait.aligned;" ::: "memory");
}

__global__ void __launch_bounds__(256, 1) __cluster_dims__(8, 1, 1)
scan_kernel(const int* __restrict__ lens, int layer) {
    extern __shared__ float sm[];
    float* wT   = sm;                       // [256][128]
    float* hbuf = sm + 256 * 128;           // [2][8][260]
    float* gsm  = hbuf + 2 * HPH;           // [128][9]

    int cta = blockIdx.x;
    int rs  = cta & 7;                      // == cluster rank
    int bs  = (cta >> 3) & 7;
    int dir = cta >> 6;
    int tid = threadIdx.x;
    float* outp = (layer == 0) ? d_out0 : d_out1;

    int us = rs * 32;                       // first unit owned by this CTA

    // ---- load this CTA's 128 gate-rows, transposed: wT[k][r], r = gate*32+ui ----
    const float* wsrc = d_whhT + (size_t)dir * HH * NR;
    for (int idx = tid; idx < 256 * 128; idx += 256) {
        int k = idx >> 7, r = idx & 127;
        int grow = (r >> 5) * 256 + us + (r & 31);
        wT[idx] = wsrc[(size_t)k * NR + grow];
    }
    // zero phase 1 (read phase of step 0)
    for (int idx = tid; idx < HPH; idx += 256) hbuf[HPH + idx] = 0.f;

    int rq = tid >> 3;                      // 0..31: row-quad (dot) == unit ui (pointwise)
    int bl = tid & 7;                       // 0..7 : local batch
    int b  = bs * 8 + bl;
    int len = lens[b];
    int gate = rq >> 3;                     // this thread's 4 rows live in one gate block
    int ui0  = (rq & 7) * 4;
    float c = 0.f;

    // precompute DSMEM base addresses of every peer's hbuf
    unsigned laddr = (unsigned)__cvta_generic_to_shared(hbuf);
    unsigned rbase[8];
#pragma unroll
    for (int p = 0; p < 8; p++)
        asm("mapa.shared::cluster.u32 %0, %1, %2;" : "=r"(rbase[p]) : "r"(laddr), "r"(p));

    cluster_sync_();                        // wT + zeroed phase visible cluster-wide

    const float* wPtr = wT + rq * 4;

    for (int s = 0; s < TT; s++) {
        int rp = (s + 1) & 1, wp = s & 1;
        int trow = (dir == 0) ? s : ((s < len) ? (len - 1 - s) : s);

        // acc init = x-gate pre-activation (4 contiguous gate rows)
        const float* xr = d_xg + (size_t)(trow * BB + b) * GN + dir * NR;
        float4 xv = *(const float4*)(xr + gate * 256 + us + ui0);
        float a0 = xv.x, a1 = xv.y, a2 = xv.z, a3 = xv.w;

        const float* hrow = hbuf + rp * HPH + bl * HROW;
#pragma unroll 4
        for (int k4 = 0; k4 < HH; k4 += 4) {
            float4 hv = *(const float4*)(hrow + k4);
            float4 w;
            w = *(const float4*)(wPtr + (k4 + 0) * 128);
            a0 += w.x * hv.x; a1 += w.y * hv.x; a2 += w.z * hv.x; a3 += w.w * hv.x;
            w = *(const float4*)(wPtr + (k4 + 1) * 128);
            a0 += w.x * hv.y; a1 += w.y * hv.y; a2 += w.z * hv.y; a3 += w.w * hv.y;
            w = *(const float4*)(wPtr + (k4 + 2) * 128);
            a0 += w.x * hv.z; a1 += w.y * hv.z; a2 += w.z * hv.z; a3 += w.w * hv.z;
            w = *(const float4*)(wPtr + (k4 + 3) * 128);
            a0 += w.x * hv.w; a1 += w.y * hv.w; a2 += w.z * hv.w; a3 += w.w * hv.w;
        }
        int rloc = rq * 4;                  // local rows rloc..rloc+3
        gsm[(rloc + 0) * 9 + bl] = a0;
        gsm[(rloc + 1) * 9 + bl] = a1;
        gsm[(rloc + 2) * 9 + bl] = a2;
        gsm[(rloc + 3) * 9 + bl] = a3;
        __syncthreads();

        // ---- pointwise: thread = (unit ui = rq, batch bl) ----
        int ui = rq;
        float gi = gsm[(     ui) * 9 + bl];
        float gf = gsm[(32 + ui) * 9 + bl];
        float gg = gsm[(64 + ui) * 9 + bl];
        float go = gsm[(96 + ui) * 9 + bl];
        float hprev = hbuf[rp * HPH + bl * HROW + us + ui];
        float si = 1.f / (1.f + expf(-gi));
        float sf = 1.f / (1.f + expf(-gf));
        float so = 1.f / (1.f + expf(-go));
        float cn = sf * c + si * tanhf(gg);
        float hn = so * tanhf(cn);
        bool  m  = (s < len);               // pack_padded freeze semantics
        c = m ? cn : c;
        float hk = m ? hn : hprev;

        // broadcast h to all 8 peers' hbuf[wp][bl][us+ui]
        unsigned off  = (unsigned)((wp * HPH + bl * HROW + us + ui) * 4);
        unsigned bits = __float_as_uint(hk);
#pragma unroll
        for (int p = 0; p < 8; p++)
            asm volatile("st.shared::cluster.b32 [%0], %1;"
                         :: "r"(rbase[p] + off), "r"(bits) : "memory");

        // bwd writes through rev (involution) -> natural time order directly
        outp[(size_t)(trow * BB + b) * 512 + dir * HH + us + ui] = m ? hn : 0.f;

        cluster_sync_();                    // orders DSMEM stores; separates phases
    }
}

// ---------------- emissions: warp per (t,b) row, 20 outputs over 512 features ----------------
__global__ void __launch_bounds__(256) emis_kernel(const float* __restrict__ Wo,
                                                   const float* __restrict__ bo) {
    int w = (blockIdx.x * 256 + threadIdx.x) >> 5;
    int lane = threadIdx.x & 31;
    if (w >= TT * BB) return;
    const float* row = d_out1 + (size_t)w * 512;
    float rv[16];
#pragma unroll
    for (int q = 0; q < 16; q++) rv[q] = row[lane + q * 32];
    for (int k = 0; k < KK; k++) {
        const float* wp = Wo + (size_t)k * 512;
        float sacc = 0.f;
#pragma unroll
        for (int q = 0; q < 16; q++) sacc += rv[q] * wp[lane + q * 32];
#pragma unroll
        for (int o = 16; o > 0; o >>= 1) sacc += __shfl_down_sync(0xffffffffu, sacc, o);
        if (lane == 0) d_emis[(size_t)w * KK + k] = sacc + bo[k];
    }
}

// ---------------- Viterbi decode: one warp per batch element (FLOAT output) ----------------
__global__ void __launch_bounds__(32) viterbi_kernel(const float* __restrict__ trans,
                                                     const float* __restrict__ startv,
                                                     const float* __restrict__ endv,
                                                     const int* __restrict__ lens,
                                                     float* __restrict__ out) {
    __shared__ float tr[KK * KK];
    __shared__ float sc[KK];
    int b = blockIdx.x;
    int lane = threadIdx.x;
    int len = lens[b];
    for (int i = lane; i < KK * KK; i += 32) tr[i] = trans[i];
    if (lane < KK) sc[lane] = startv[lane] + d_emis[(size_t)(0 * BB + b) * KK + lane];
    __syncwarp();
    for (int t = 1; t < TT; t++) {
        if (t < len) {                     // padded steps: score frozen, identity ptr
            float best = -1e30f; int arg = 0;
            if (lane < KK) {
#pragma unroll
                for (int p = 0; p < KK; p++) {
                    float v = sc[p] + tr[p * KK + lane];
                    if (v > best) { best = v; arg = p; }   // first-max (jnp.argmax)
                }
                best += d_emis[(size_t)(t * BB + b) * KK + lane];
            }
            __syncwarp();
            if (lane < KK) {
                sc[lane] = best;
                d_vptr[(size_t)((t - 1) * BB + b) * KK + lane] = arg;
            }
            __syncwarp();
        }
    }
    if (lane == 0) {
        float bb = -1e30f; int last = 0;
        for (int k = 0; k < KK; k++) {
            float v = sc[k] + endv[k];
            if (v > bb) { bb = v; last = k; }
        }
        int tag = last;
        for (int t = TT - 1; t >= 1; --t) {
            if (t < len) {
                out[t * BB + b] = (float)tag;
                tag = d_vptr[(size_t)((t - 1) * BB + b) * KK + tag];
            } else {
                out[t * BB + b] = 0.f;     // identity ptr passes tag through; masked to 0
            }
        }
        out[b] = (float)tag;               // t = 0 always valid (len >= 128)
    }
}

// ---------------- launch ----------------
extern "C" void kernel_launch(void* const* d_in, const int* in_sizes, int n_in,
                              void* d_out, int out_size) {
    // Bind inputs by stable size-match against the expected setup_inputs dict order.
    static const long long want[14] = {
        (long long)TT * BB,            // x              16384 (int32)
        BB,                            // sent_lengths   64    (int32)
        50000LL * EE,                  // emb            15,000,000
        2LL * NR * EE,                 // Wih0           614,400
        2LL * NR * HH,                 // Whh0           524,288
        2LL * NR,                      // b0             2,048
        2LL * NR * 2 * HH,             // Wih1           1,048,576
        2LL * NR * HH,                 // Whh1           524,288
        2LL * NR,                      // b1             2,048
        (long long)KK * 2 * HH,        // W_out          10,240
        KK,                            // b_out          20
        (long long)KK * KK,            // trans          400
        KK,                            // start          20
        KK                             // end            20
    };
    const void* p[14];
    bool used[64] = {false};
    for (int i = 0; i < 14; i++) {
        p[i] = nullptr;
        for (int k = 0; k < n_in && k < 64; k++) {
            if (!used[k] && (long long)in_sizes[k] == want[i]) {
                p[i] = d_in[k]; used[k] = true; break;
            }
        }
        if (!p[i] && i < n_in) p[i] = d_in[i];   // fallback: positional
    }
    const int*   x      = (const int*)p[0];
    const int*   lens   = (const int*)p[1];
    const float* emb    = (const float*)p[2];
    const float* Wih0   = (const float*)p[3];
    const float* Whh0   = (const float*)p[4];
    const float* b0     = (const float*)p[5];
    const float* Wih1   = (const float*)p[6];
    const float* Whh1   = (const float*)p[7];
    const float* b1     = (const float*)p[8];
    const float* Wout   = (const float*)p[9];
    const float* bout   = (const float*)p[10];
    const float* trans  = (const float*)p[11];
    const float* startv = (const float*)p[12];
    const float* endv   = (const float*)p[13];
    float* out = (float*)d_out;

    const int smem_bytes = SM_FLOATS * 4;   // 152,320 B
    cudaFuncSetAttribute(scan_kernel, cudaFuncAttributeMaxDynamicSharedMemorySize, smem_bytes);

    dim3 tgrid(32, 8, 2);   // Whh transpose tiles

    emb_kernel<<<TT * BB, 128>>>(x, emb);

    // ---- layer 0 ----
    gemm_xg<<<dim3(GN / BN, (TT * BB) / BM), 256>>>(Wih0, b0, 0, EE);
    transpose_whh<<<tgrid, 256>>>(Whh0);
    scan_kernel<<<128, 256, smem_bytes>>>(lens, 0);

    // ---- layer 1 ----
    gemm_xg<<<dim3(GN / BN, (TT * BB) / BM), 256>>>(Wih1, b1, 1, 2 * HH);
    transpose_whh<<<tgrid, 256>>>(Whh1);
    scan_kernel<<<128, 256, smem_bytes>>>(lens, 1);

    // ---- emissions + CRF decode ----
    emis_kernel<<<(TT * BB) / 8, 256>>>(Wout, bout);
    viterbi_kernel<<<BB, 32>>>(trans, startv, endv, lens, out);
}

// round 16
// speedup vs baseline: 2.3196x; 1.0733x over previous
#include <cuda_runtime.h>
#include <cuda_bf16.h>
#include <math.h>

// Problem constants
#define TT 256
#define BB 64
#define EE 300
#define HH 256
#define KK 20
#define GN 2048   // concat gate width: 2 dirs * 4 gates * H
#define NR 1024   // gate rows per direction (4*H)

// ---------------- scratch (__device__ globals: allocation-free, zero-init) ----------------
__device__ float d_embx[(size_t)TT * BB * EE];      // embedded input  [T*B, 300]
__device__ float d_xg  [(size_t)TT * BB * GN];      // gate pre-acts   [T*B, 2048] (reused per layer)
__device__ float d_out0[(size_t)TT * BB * 512];     // layer0 output   [T*B, 512]
__device__ float d_out1[(size_t)TT * BB * 512];     // layer1 output   [T*B, 512]
__device__ float d_emis[(size_t)TT * BB * KK];      // emissions       [T*B, 20]
__device__ float d_whhT[2 * HH * NR];               // transposed Whh  [dir][j][row]
__device__ int   d_vptr[(size_t)TT * BB * KK];      // viterbi backpointers

// ---------------- embedding gather ----------------
__global__ void __launch_bounds__(128) emb_kernel(const int* __restrict__ x,
                                                  const float* __restrict__ emb) {
    int row = blockIdx.x;                 // row = t*B + b
    int tok = x[row];
    const float* s = emb + (size_t)tok * EE;
    float* d = d_embx + (size_t)row * EE;
    for (int e = threadIdx.x; e < EE; e += 128) d[e] = s[e];
}

// ---------------- input-projection GEMM: C[M,2048] = A[M,K] @ W[2048,K]^T + bias ----------------
#define BM 64
#define BN 64
#define BKT 16
__global__ void __launch_bounds__(256) gemm_xg(const float* __restrict__ Bw,
                                               const float* __restrict__ bias,
                                               int layer, int K) {
    const float* A = (layer == 0) ? d_embx : d_out0;
    __shared__ float As[BKT][BM + 4];
    __shared__ float Bs[BKT][BN + 4];
    int m0 = blockIdx.y * BM;
    int n0 = blockIdx.x * BN;
    int tid = threadIdx.x;
    int tx = tid & 15, ty = tid >> 4;
    float acc[4][4];
#pragma unroll
    for (int i = 0; i < 4; i++)
#pragma unroll
        for (int j = 0; j < 4; j++) acc[i][j] = 0.f;

    for (int k0 = 0; k0 < K; k0 += BKT) {
#pragma unroll
        for (int r = 0; r < 4; r++) {
            int idx = tid + r * 256;       // 0..1023
            int mm = idx >> 4;             // 0..63
            int kk = idx & 15;
            int kg = k0 + kk;
            As[kk][mm] = (kg < K) ? A [(size_t)(m0 + mm) * K + kg] : 0.f;
            Bs[kk][mm] = (kg < K) ? Bw[(size_t)(n0 + mm) * K + kg] : 0.f;
        }
        __syncthreads();
#pragma unroll
        for (int k = 0; k < BKT; k++) {
            float4 a4 = *(const float4*)&As[k][ty * 4];
            float4 b4 = *(const float4*)&Bs[k][tx * 4];
            float a[4] = {a4.x, a4.y, a4.z, a4.w};
            float b[4] = {b4.x, b4.y, b4.z, b4.w};
#pragma unroll
            for (int i = 0; i < 4; i++)
#pragma unroll
                for (int j = 0; j < 4; j++) acc[i][j] += a[i] * b[j];
        }
        __syncthreads();
    }
#pragma unroll
    for (int i = 0; i < 4; i++) {
        int m = m0 + ty * 4 + i;
#pragma unroll
        for (int j = 0; j < 4; j++) {
            int n = n0 + tx * 4 + j;
            d_xg[(size_t)m * GN + n] = acc[i][j] + bias[n];
        }
    }
}

// ---------------- Whh transpose: [dir][row 1024][j 256] -> d_whhT [dir][j 256][row 1024] ----------------
__global__ void __launch_bounds__(256) transpose_whh(const float* __restrict__ W) {
    __shared__ float t[32][33];
    int dir = blockIdx.z;
    int r0 = blockIdx.x * 32;      // row tile (gridDim.x = 32)
    int j0 = blockIdx.y * 32;      // col tile (gridDim.y = 8)
    int tx = threadIdx.x & 31;
    int ty = threadIdx.x >> 5;     // 0..7
#pragma unroll
    for (int k = 0; k < 32; k += 8)
        t[ty + k][tx] = W[(size_t)dir * NR * HH + (size_t)(r0 + ty + k) * HH + (j0 + tx)];
    __syncthreads();
#pragma unroll
    for (int k = 0; k < 32; k += 8)
        d_whhT[(size_t)dir * HH * NR + (size_t)(j0 + ty + k) * NR + (r0 + tx)] = t[tx][ty + k];
}

// ---------------- persistent cluster scan, v2 ----------------
// grid = 128 CTAs: cta = dir*64 + bs*8 + rs. Cluster (8 CTAs) = one (dir, bs)
// group; rank rs owns units [rs*32, rs*32+32) i.e. 128 gate-rows. 512 threads.
//
// Dot thread map: kh = tid>>6 (k-slice of 32), rq = (tid&63)>>1 (4 rows),
// bg = tid&1 (4 batches). Per k-iter: one w float4 (rows) + one h float4
// (batches) -> 16 FFMA into acc[4][4]. A warp holds a single k per iter:
// w-loads 256B contiguous, h-loads broadcast -> no k-stride bank aliasing.
// Partials reduced through gsm[8][128][12], then 256 pointwise threads
// (bl = tid>>5, ui = tid&31; coalesced output) apply gates + freeze and
// broadcast h to all 8 peers via DSMEM, double-buffered, barrier.cluster/step.
//
// SMEM (floats): wT[256][128]=32768  hbuf[2][256][8]=4096  gsm[8][128][12]=12288
#define GSP 12
#define SM_FLOATS (256 * 128 + 2 * 256 * 8 + 8 * 128 * GSP)

__device__ __forceinline__ void cluster_sync_() {
    asm volatile("barrier.cluster.arrive.aligned;" ::: "memory");
    asm volatile("barrier.cluster.wait.aligned;" ::: "memory");
}

__global__ void __launch_bounds__(512, 1) __cluster_dims__(8, 1, 1)
scan_kernel(const int* __restrict__ lens, int layer) {
    extern __shared__ float sm[];
    float* wT   = sm;                       // [256][128]  wT[k][r]
    float* hbuf = sm + 256 * 128;           // [2][256][8] hbuf[ph][u][b]
    float* gsm  = hbuf + 2 * 256 * 8;       // [8][128][GSP]

    int cta = blockIdx.x;
    int rs  = cta & 7;                      // == cluster rank
    int bs  = (cta >> 3) & 7;
    int dir = cta >> 6;
    int tid = threadIdx.x;
    float* outp = (layer == 0) ? d_out0 : d_out1;

    int us = rs * 32;                       // first unit owned by this CTA

    // ---- load this CTA's 128 gate-rows, transposed: wT[k][r], r = gate*32+ui ----
    const float* wsrc = d_whhT + (size_t)dir * HH * NR;
    for (int idx = tid; idx < 256 * 128; idx += 512) {
        int k = idx >> 7, r = idx & 127;
        int grow = (r >> 5) * 256 + us + (r & 31);
        wT[idx] = wsrc[(size_t)k * NR + grow];
    }
    // zero phase 1 (read phase of step 0)
    for (int idx = tid; idx < 256 * 8; idx += 512) hbuf[256 * 8 + idx] = 0.f;

    // dot-phase thread coordinates
    int kh = tid >> 6;                      // 0..7
    int rq = (tid & 63) >> 1;               // 0..31  -> rows rq*4..+3
    int bg = tid & 1;                       // 0..1   -> batches bg*4..+3
    // pointwise-phase coordinates (tid < 256)
    int bl = tid >> 5;                      // 0..7
    int ui = tid & 31;                      // 0..31
    int b  = bs * 8 + bl;
    int len = (tid < 256) ? lens[b] : 0;
    float c = 0.f;

    // DSMEM base addresses of every peer's hbuf
    unsigned laddr = (unsigned)__cvta_generic_to_shared(hbuf);
    unsigned rbase[8];
#pragma unroll
    for (int p = 0; p < 8; p++)
        asm("mapa.shared::cluster.u32 %0, %1, %2;" : "=r"(rbase[p]) : "r"(laddr), "r"(p));

    cluster_sync_();                        // wT + zeroed phase visible cluster-wide

    const int kbase = kh * 32;

    for (int s = 0; s < TT; s++) {
        int rp = (s + 1) & 1, wp = s & 1;

        // ---- dot: acc[ri][bi] over this thread's 32-k slice ----
        float a00=0.f,a01=0.f,a02=0.f,a03=0.f;
        float a10=0.f,a11=0.f,a12=0.f,a13=0.f;
        float a20=0.f,a21=0.f,a22=0.f,a23=0.f;
        float a30=0.f,a31=0.f,a32=0.f,a33=0.f;
        const float* wp_ = wT + (size_t)kbase * 128 + rq * 4;
        const float* hp_ = hbuf + rp * 2048 + kbase * 8 + bg * 4;
#pragma unroll 8
        for (int j = 0; j < 32; j++) {
            float4 w4 = *(const float4*)(wp_ + j * 128);
            float4 h4 = *(const float4*)(hp_ + j * 8);
            a00 += w4.x * h4.x; a01 += w4.x * h4.y; a02 += w4.x * h4.z; a03 += w4.x * h4.w;
            a10 += w4.y * h4.x; a11 += w4.y * h4.y; a12 += w4.y * h4.z; a13 += w4.y * h4.w;
            a20 += w4.z * h4.x; a21 += w4.z * h4.y; a22 += w4.z * h4.z; a23 += w4.z * h4.w;
            a30 += w4.w * h4.x; a31 += w4.w * h4.y; a32 += w4.w * h4.z; a33 += w4.w * h4.w;
        }
        {
            float* g0 = gsm + (size_t)(kh * 128 + rq * 4) * GSP + bg * 4;
            *(float4*)(g0 + 0 * GSP) = make_float4(a00, a01, a02, a03);
            *(float4*)(g0 + 1 * GSP) = make_float4(a10, a11, a12, a13);
            *(float4*)(g0 + 2 * GSP) = make_float4(a20, a21, a22, a23);
            *(float4*)(g0 + 3 * GSP) = make_float4(a30, a31, a32, a33);
        }
        __syncthreads();

        // ---- pointwise: thread = (bl, ui), tid < 256 ----
        if (tid < 256) {
            int trow = (dir == 0) ? s : ((s < len) ? (len - 1 - s) : s);
            float gi = 0.f, gf = 0.f, gg = 0.f, go = 0.f;
#pragma unroll
            for (int q = 0; q < 8; q++) {
                const float* gp = gsm + (size_t)(q * 128) * GSP + bl;
                gi += gp[(      ui) * GSP];
                gf += gp[(32  + ui) * GSP];
                gg += gp[(64  + ui) * GSP];
                go += gp[(96  + ui) * GSP];
            }
            const float* xr = d_xg + (size_t)(trow * BB + b) * GN + dir * NR;
            gi += xr[      us + ui];
            gf += xr[256 + us + ui];
            gg += xr[512 + us + ui];
            go += xr[768 + us + ui];

            float hprev = hbuf[rp * 2048 + (us + ui) * 8 + bl];
            float si = 1.f / (1.f + expf(-gi));
            float sf = 1.f / (1.f + expf(-gf));
            float so = 1.f / (1.f + expf(-go));
            float cn = sf * c + si * tanhf(gg);
            float hn = so * tanhf(cn);
            bool  m  = (s < len);               // pack_padded freeze semantics
            c = m ? cn : c;
            float hk = m ? hn : hprev;

            // broadcast h to all 8 peers' hbuf[wp][us+ui][bl]
            unsigned off  = (unsigned)((wp * 2048 + (us + ui) * 8 + bl) * 4);
            unsigned bits = __float_as_uint(hk);
#pragma unroll
            for (int p = 0; p < 8; p++)
                asm volatile("st.shared::cluster.b32 [%0], %1;"
                             :: "r"(rbase[p] + off), "r"(bits) : "memory");

            // bwd writes through rev (involution) -> natural time order directly
            outp[(size_t)(trow * BB + b) * 512 + dir * HH + us + ui] = m ? hn : 0.f;
        }
        cluster_sync_();                    // orders DSMEM stores; separates phases
    }
}

// ---------------- emissions: warp per (t,b) row, 20 outputs over 512 features ----------------
__global__ void __launch_bounds__(256) emis_kernel(const float* __restrict__ Wo,
                                                   const float* __restrict__ bo) {
    int w = (blockIdx.x * 256 + threadIdx.x) >> 5;
    int lane = threadIdx.x & 31;
    if (w >= TT * BB) return;
    const float* row = d_out1 + (size_t)w * 512;
    float rv[16];
#pragma unroll
    for (int q = 0; q < 16; q++) rv[q] = row[lane + q * 32];
    for (int k = 0; k < KK; k++) {
        const float* wp = Wo + (size_t)k * 512;
        float sacc = 0.f;
#pragma unroll
        for (int q = 0; q < 16; q++) sacc += rv[q] * wp[lane + q * 32];
#pragma unroll
        for (int o = 16; o > 0; o >>= 1) sacc += __shfl_down_sync(0xffffffffu, sacc, o);
        if (lane == 0) d_emis[(size_t)w * KK + k] = sacc + bo[k];
    }
}

// ---------------- Viterbi decode: one warp per batch element (FLOAT output) ----------------
__global__ void __launch_bounds__(32) viterbi_kernel(const float* __restrict__ trans,
                                                     const float* __restrict__ startv,
                                                     const float* __restrict__ endv,
                                                     const int* __restrict__ lens,
                                                     float* __restrict__ out) {
    __shared__ float tr[KK * KK];
    __shared__ float sc[KK];
    int b = blockIdx.x;
    int lane = threadIdx.x;
    int len = lens[b];
    for (int i = lane; i < KK * KK; i += 32) tr[i] = trans[i];
    if (lane < KK) sc[lane] = startv[lane] + d_emis[(size_t)(0 * BB + b) * KK + lane];
    __syncwarp();
    for (int t = 1; t < TT; t++) {
        if (t < len) {                     // padded steps: score frozen, identity ptr
            float best = -1e30f; int arg = 0;
            if (lane < KK) {
#pragma unroll
                for (int p = 0; p < KK; p++) {
                    float v = sc[p] + tr[p * KK + lane];
                    if (v > best) { best = v; arg = p; }   // first-max (jnp.argmax)
                }
                best += d_emis[(size_t)(t * BB + b) * KK + lane];
            }
            __syncwarp();
            if (lane < KK) {
                sc[lane] = best;
                d_vptr[(size_t)((t - 1) * BB + b) * KK + lane] = arg;
            }
            __syncwarp();
        }
    }
    if (lane == 0) {
        float bb = -1e30f; int last = 0;
        for (int k = 0; k < KK; k++) {
            float v = sc[k] + endv[k];
            if (v > bb) { bb = v; last = k; }
        }
        int tag = last;
        for (int t = TT - 1; t >= 1; --t) {
            if (t < len) {
                out[t * BB + b] = (float)tag;
                tag = d_vptr[(size_t)((t - 1) * BB + b) * KK + tag];
            } else {
                out[t * BB + b] = 0.f;     // identity ptr passes tag through; masked to 0
            }
        }
        out[b] = (float)tag;               // t = 0 always valid (len >= 128)
    }
}

// ---------------- launch ----------------
extern "C" void kernel_launch(void* const* d_in, const int* in_sizes, int n_in,
                              void* d_out, int out_size) {
    // Bind inputs by stable size-match against the expected setup_inputs dict order.
    static const long long want[14] = {
        (long long)TT * BB,            // x              16384 (int32)
        BB,                            // sent_lengths   64    (int32)
        50000LL * EE,                  // emb            15,000,000
        2LL * NR * EE,                 // Wih0           614,400
        2LL * NR * HH,                 // Whh0           524,288
        2LL * NR,                      // b0             2,048
        2LL * NR * 2 * HH,             // Wih1           1,048,576
        2LL * NR * HH,                 // Whh1           524,288
        2LL * NR,                      // b1             2,048
        (long long)KK * 2 * HH,        // W_out          10,240
        KK,                            // b_out          20
        (long long)KK * KK,            // trans          400
        KK,                            // start          20
        KK                             // end            20
    };
    const void* p[14];
    bool used[64] = {false};
    for (int i = 0; i < 14; i++) {
        p[i] = nullptr;
        for (int k = 0; k < n_in && k < 64; k++) {
            if (!used[k] && (long long)in_sizes[k] == want[i]) {
                p[i] = d_in[k]; used[k] = true; break;
            }
        }
        if (!p[i] && i < n_in) p[i] = d_in[i];   // fallback: positional
    }
    const int*   x      = (const int*)p[0];
    const int*   lens   = (const int*)p[1];
    const float* emb    = (const float*)p[2];
    const float* Wih0   = (const float*)p[3];
    const float* Whh0   = (const float*)p[4];
    const float* b0     = (const float*)p[5];
    const float* Wih1   = (const float*)p[6];
    const float* Whh1   = (const float*)p[7];
    const float* b1     = (const float*)p[8];
    const float* Wout   = (const float*)p[9];
    const float* bout   = (const float*)p[10];
    const float* trans  = (const float*)p[11];
    const float* startv = (const float*)p[12];
    const float* endv   = (const float*)p[13];
    float* out = (float*)d_out;

    const int smem_bytes = SM_FLOATS * 4;   // 196,608 B
    cudaFuncSetAttribute(scan_kernel, cudaFuncAttributeMaxDynamicSharedMemorySize, smem_bytes);

    dim3 tgrid(32, 8, 2);   // Whh transpose tiles

    emb_kernel<<<TT * BB, 128>>>(x, emb);

    // ---- layer 0 ----
    gemm_xg<<<dim3(GN / BN, (TT * BB) / BM), 256>>>(Wih0, b0, 0, EE);
    transpose_whh<<<tgrid, 256>>>(Whh0);
    scan_kernel<<<128, 512, smem_bytes>>>(lens, 0);

    // ---- layer 1 ----
    gemm_xg<<<dim3(GN / BN, (TT * BB) / BM), 256>>>(Wih1, b1, 1, 2 * HH);
    transpose_whh<<<tgrid, 256>>>(Whh1);
    scan_kernel<<<128, 512, smem_bytes>>>(lens, 1);

    // ---- emissions + CRF decode ----
    emis_kernel<<<(TT * BB) / 8, 256>>>(Wout, bout);
    viterbi_kernel<<<BB, 32>>>(trans, startv, endv, lens, out);
}